// round 7
// baseline (speedup 1.0000x reference)
#include <cuda_runtime.h>
#include <cuda_bf16.h>
#include <math.h>
#include <stdint.h>

#define T_TOK 2048
#define DDIM  2048
#define FDIM  4096
#define NEXP  8

#define NSTG 3
#define BS_STRIDE_GU 136 // fp32 B stage: 32 rows x 128 cols padded
#define BS_STRIDE_DN 72  // fp32 B stage: 32 rows x 64 cols padded

// bf16 tile layouts: [row-or-col][k], stride 40 halfs (80 B) -> conflict-free frags
#define BF_STRIDE 40
#define A16_STAGE 10240            // 128 * 80 B
#define BF32_STAGE_GU (32 * BS_STRIDE_GU * 4)   // 17408
#define BF32_STAGE_DN (32 * BS_STRIDE_DN * 4)   // 9216

// GU smem offsets
#define GU_AHI 0
#define GU_ALO (GU_AHI + NSTG * A16_STAGE)          // 30720
#define GU_BF  (GU_ALO + NSTG * A16_STAGE)          // 61440
#define GU_BHI (GU_BF + NSTG * BF32_STAGE_GU)       // 113664
#define GU_BLO (GU_BHI + 128 * 80)                  // 123904
#define SMEM_GU (GU_BLO + 128 * 80)                 // 134144

// DN smem offsets
#define DN_AHI 0
#define DN_ALO (DN_AHI + NSTG * A16_STAGE)          // 30720
#define DN_BF  (DN_ALO + NSTG * A16_STAGE)          // 61440
#define DN_BHI (DN_BF + NSTG * BF32_STAGE_DN)       // 89088
#define DN_BLO (DN_BHI + 64 * 80)                   // 94208
#define SMEM_DN (DN_BLO + 64 * 80)                  // 99328

// ---- static scratch ----
__device__ int   g_cnt[NEXP];
__device__ int   g_eid[T_TOK];
__device__ float g_w[T_TOK];
__device__ int   g_list[NEXP * T_TOK];
__device__ __nv_bfloat16 g_xhi[(size_t)T_TOK * DDIM];
__device__ __nv_bfloat16 g_xlo[(size_t)T_TOK * DDIM];
__device__ __nv_bfloat16 g_hhi[(size_t)T_TOK * FDIM];
__device__ __nv_bfloat16 g_hlo[(size_t)T_TOK * FDIM];
__device__ __nv_bfloat16 g_hshi[(size_t)T_TOK * FDIM];
__device__ __nv_bfloat16 g_hslo[(size_t)T_TOK * FDIM];

// ---- helpers ----
__device__ __forceinline__ uint32_t smem_u32(const void* p) {
    uint32_t a;
    asm("{ .reg .u64 t; cvta.to.shared.u64 t, %1; cvt.u32.u64 %0, t; }"
        : "=r"(a) : "l"(p));
    return a;
}

__device__ __forceinline__ void cpa16(uint32_t dst, const void* src, int srcsz) {
    asm volatile("cp.async.cg.shared.global [%0], [%1], 16, %2;"
                 :: "r"(dst), "l"(src), "r"(srcsz) : "memory");
}
#define CP_COMMIT() asm volatile("cp.async.commit_group;" ::: "memory")
#define CP_WAIT1()  asm volatile("cp.async.wait_group 1;" ::: "memory")

#define MMA_BF16(d, a, b) \
    asm volatile("mma.sync.aligned.m16n8k16.row.col.f32.bf16.bf16.f32 " \
        "{%0,%1,%2,%3}, {%4,%5,%6,%7}, {%8,%9}, {%0,%1,%2,%3};" \
        : "+f"((d)[0]), "+f"((d)[1]), "+f"((d)[2]), "+f"((d)[3]) \
        : "r"((a)[0]), "r"((a)[1]), "r"((a)[2]), "r"((a)[3]), \
          "r"((b)[0]), "r"((b)[1]))

// split float2 (f.x -> low half, f.y -> high half) into hi bf16x2 and lo residual bf16x2
__device__ __forceinline__ void bf16_split2(float2 f, uint32_t& hi, uint32_t& lo) {
    uint32_t h;
    asm("cvt.rn.bf16x2.f32 %0, %1, %2;" : "=r"(h) : "f"(f.y), "f"(f.x));
    float hx = __uint_as_float(h << 16);
    float hy = __uint_as_float(h & 0xffff0000u);
    asm("cvt.rn.bf16x2.f32 %0, %1, %2;" : "=r"(lo) : "f"(f.y - hy), "f"(f.x - hx));
    hi = h;
}

__device__ __forceinline__ float silu_f(float g) {
    return g / (1.f + __expf(-g));
}

// ---- routing ----
__global__ void zero_counts() {
    if (threadIdx.x < NEXP) g_cnt[threadIdx.x] = 0;
}

__global__ void router_kernel(const float* __restrict__ x,
                              const float* __restrict__ rw) {
    int t = blockIdx.x * blockDim.y + threadIdx.y;
    if (t >= T_TOK) return;
    int lane = threadIdx.x;
    float acc[NEXP];
#pragma unroll
    for (int e = 0; e < NEXP; e++) acc[e] = 0.f;
    const float* xr = x + (size_t)t * DDIM;
    for (int d = lane; d < DDIM; d += 32) {
        float xv = xr[d];
        const float4* r = (const float4*)(rw + (size_t)d * NEXP);
        float4 r0 = r[0], r1 = r[1];
        acc[0] += xv * r0.x; acc[1] += xv * r0.y;
        acc[2] += xv * r0.z; acc[3] += xv * r0.w;
        acc[4] += xv * r1.x; acc[5] += xv * r1.y;
        acc[6] += xv * r1.z; acc[7] += xv * r1.w;
    }
#pragma unroll
    for (int off = 16; off > 0; off >>= 1)
#pragma unroll
        for (int e = 0; e < NEXP; e++)
            acc[e] += __shfl_down_sync(0xffffffffu, acc[e], off);
    if (lane == 0) {
        int best = 0; float bv = acc[0];
#pragma unroll
        for (int e = 1; e < NEXP; e++)
            if (acc[e] > bv) { bv = acc[e]; best = e; }
        g_eid[t] = best;
        g_w[t]   = 1.f / (1.f + expf(-bv));
    }
}

__global__ void scatter_kernel() {
    int t = blockIdx.x * blockDim.x + threadIdx.x;
    if (t < T_TOK) {
        int e = g_eid[t];
        int p = atomicAdd(&g_cnt[e], 1);
        g_list[e * T_TOK + p] = t;
    }
}

// convert x -> bf16 hi/lo
__global__ void convert_x(const float* __restrict__ x) {
    int i = blockIdx.x * blockDim.x + threadIdx.x;   // over T*D/2
    float2 f = ((const float2*)x)[i];
    uint32_t hi, lo;
    bf16_split2(f, hi, lo);
    ((uint32_t*)g_xhi)[i] = hi;
    ((uint32_t*)g_xlo)[i] = lo;
}

// ================= gate+up GEMM =================
template<bool SHARED>
__global__ void __launch_bounds__(256)
gu_kernel(const float* __restrict__ wgA,
          const float* __restrict__ wuA,
          __nv_bfloat16* __restrict__ hhi,
          __nv_bfloat16* __restrict__ hlo) {
    int e   = SHARED ? 0 : blockIdx.z;
    int cnt = SHARED ? T_TOK : g_cnt[e];
    int m0  = blockIdx.y * 128;
    if (m0 >= cnt) return;
    int n0  = blockIdx.x * 64;
    const float* wg = wgA + (SHARED ? 0 : (size_t)e * DDIM * FDIM);
    const float* wu = wuA + (SHARED ? 0 : (size_t)e * DDIM * FDIM);

    extern __shared__ char dyn[];
    __shared__ int toks[128];
    int tid = threadIdx.x;
    if (tid < 128) {
        int m = m0 + tid;
        toks[tid] = (m < cnt) ? (SHARED ? m : g_list[e * T_TOK + m]) : -1;
    }
    __syncthreads();

    uint32_t smb = smem_u32(dyn);

    // A loads (bf16 hi/lo): 512 chunks of 16B each array; 2 per thread per array
    const __nv_bfloat16* ahsrc[2];
    const __nv_bfloat16* alsrc[2];
    int apred[2];
    uint32_t adst[2];
#pragma unroll
    for (int i = 0; i < 2; i++) {
        int s = tid * 2 + i;
        int row = s >> 2, q = s & 3;
        int tk = toks[row];
        apred[i] = (tk >= 0) ? 16 : 0;
        size_t off = (tk >= 0) ? ((size_t)tk * DDIM + q * 8) : 0;
        ahsrc[i] = g_xhi + off;
        alsrc[i] = g_xlo + off;
        adst[i]  = row * 80 + q * 16;
    }
    // B loads (fp32): 1024 chunks, 4 per thread
    const float* bsrc[4];
    uint32_t bdst[4];
#pragma unroll
    for (int i = 0; i < 4; i++) {
        int s = tid + 256 * i;
        int row = s >> 5, chk = s & 31;
        const float* base = (chk < 16) ? (wg + n0 + chk * 4)
                                       : (wu + n0 + (chk - 16) * 4);
        bsrc[i] = base + (size_t)row * FDIM;
        bdst[i] = (row * BS_STRIDE_GU + (chk & 15) * 4 + (chk < 16 ? 0 : 64)) * 4;
    }

    auto load_stage = [&](int kc, int st) {
        int k0 = kc * 32;
        uint32_t ah = smb + GU_AHI + st * A16_STAGE;
        uint32_t al = smb + GU_ALO + st * A16_STAGE;
#pragma unroll
        for (int i = 0; i < 2; i++) {
            cpa16(ah + adst[i], ahsrc[i] + k0, apred[i]);
            cpa16(al + adst[i], alsrc[i] + k0, apred[i]);
        }
        uint32_t bb = smb + GU_BF + st * BF32_STAGE_GU;
#pragma unroll
        for (int i = 0; i < 4; i++)
            cpa16(bb + bdst[i], bsrc[i] + (size_t)k0 * FDIM, 16);
        CP_COMMIT();
    };

    int wid = tid >> 5, lane = tid & 31;
    int wm = (wid >> 1) * 32;
    int wn = (wid & 1) * 32;
    int gr = lane >> 2, gc = lane & 3;

    float acc[2][8][4];
#pragma unroll
    for (int mt = 0; mt < 2; mt++)
#pragma unroll
        for (int nt = 0; nt < 8; nt++)
#pragma unroll
            for (int j = 0; j < 4; j++) acc[mt][nt][j] = 0.f;

    const int NKC = DDIM / 32;  // 64
    load_stage(0, 0);
    load_stage(1, 1);

    int ccol = tid >> 1, ckh = (tid & 1) * 16;
    uint32_t* bhu = (uint32_t*)(dyn + GU_BHI);
    uint32_t* blu = (uint32_t*)(dyn + GU_BLO);

    for (int kc = 0; kc < NKC; kc++) {
        CP_WAIT1();
        __syncthreads();
        if (kc + 2 < NKC) load_stage(kc + 2, (kc + 2) % NSTG);

        // convert B fp32 [k][col] -> bf16 hi/lo [col][k]
        {
            const float* Bf = (const float*)(dyn + GU_BF + (kc % NSTG) * BF32_STAGE_GU);
#pragma unroll
            for (int k2 = 0; k2 < 8; k2++) {
                float f0 = Bf[(ckh + 2 * k2) * BS_STRIDE_GU + ccol];
                float f1 = Bf[(ckh + 2 * k2 + 1) * BS_STRIDE_GU + ccol];
                uint32_t hi, lo;
                bf16_split2(make_float2(f0, f1), hi, lo);
                bhu[ccol * 20 + (ckh >> 1) + k2] = hi;
                blu[ccol * 20 + (ckh >> 1) + k2] = lo;
            }
        }
        __syncthreads();

        const __nv_bfloat16* Ah = (const __nv_bfloat16*)(dyn + GU_AHI + (kc % NSTG) * A16_STAGE);
        const __nv_bfloat16* Al = (const __nv_bfloat16*)(dyn + GU_ALO + (kc % NSTG) * A16_STAGE);
        const __nv_bfloat16* Bh = (const __nv_bfloat16*)(dyn + GU_BHI);
        const __nv_bfloat16* Bl = (const __nv_bfloat16*)(dyn + GU_BLO);
#pragma unroll
        for (int ks = 0; ks < 2; ks++) {
            uint32_t a_hi[2][4], a_lo[2][4];
#pragma unroll
            for (int mt = 0; mt < 2; mt++) {
                int base = (wm + mt * 16 + gr) * BF_STRIDE + ks * 16 + gc * 2;
                a_hi[mt][0] = *(const uint32_t*)(Ah + base);
                a_hi[mt][1] = *(const uint32_t*)(Ah + base + 8 * BF_STRIDE);
                a_hi[mt][2] = *(const uint32_t*)(Ah + base + 8);
                a_hi[mt][3] = *(const uint32_t*)(Ah + base + 8 * BF_STRIDE + 8);
                a_lo[mt][0] = *(const uint32_t*)(Al + base);
                a_lo[mt][1] = *(const uint32_t*)(Al + base + 8 * BF_STRIDE);
                a_lo[mt][2] = *(const uint32_t*)(Al + base + 8);
                a_lo[mt][3] = *(const uint32_t*)(Al + base + 8 * BF_STRIDE + 8);
            }
#pragma unroll
            for (int nt = 0; nt < 8; nt++) {
                int col = (nt < 4) ? (wn + nt * 8 + gr) : (64 + wn + (nt - 4) * 8 + gr);
                int bbase = col * BF_STRIDE + ks * 16 + gc * 2;
                uint32_t b_hi[2], b_lo[2];
                b_hi[0] = *(const uint32_t*)(Bh + bbase);
                b_hi[1] = *(const uint32_t*)(Bh + bbase + 8);
                b_lo[0] = *(const uint32_t*)(Bl + bbase);
                b_lo[1] = *(const uint32_t*)(Bl + bbase + 8);
#pragma unroll
                for (int mt = 0; mt < 2; mt++) {
                    MMA_BF16(acc[mt][nt], a_hi[mt], b_lo);
                    MMA_BF16(acc[mt][nt], a_lo[mt], b_hi);
                    MMA_BF16(acc[mt][nt], a_hi[mt], b_hi);
                }
            }
        }
        __syncthreads();
    }

    // epilogue: silu(gate)*up -> h hi/lo bf16
    uint32_t* hh = (uint32_t*)hhi;
    uint32_t* hl = (uint32_t*)hlo;
#pragma unroll
    for (int mt = 0; mt < 2; mt++) {
#pragma unroll
        for (int half = 0; half < 2; half++) {
            int row = wm + mt * 16 + gr + half * 8;
            int tk = toks[row];
            if (tk < 0) continue;
            size_t rb = ((size_t)tk * FDIM + n0 + wn) >> 1;
#pragma unroll
            for (int nt = 0; nt < 4; nt++) {
                float2 v;
                v.x = silu_f(acc[mt][nt][half * 2 + 0]) * acc[mt][nt + 4][half * 2 + 0];
                v.y = silu_f(acc[mt][nt][half * 2 + 1]) * acc[mt][nt + 4][half * 2 + 1];
                uint32_t hi, lo;
                bf16_split2(v, hi, lo);
                size_t idx = rb + ((nt * 8 + gc * 2) >> 1);
                hh[idx] = hi;
                hl[idx] = lo;
            }
        }
    }
}

// ================= down GEMM =================
template<bool SHARED>
__global__ void __launch_bounds__(256)
dn_kernel(const __nv_bfloat16* __restrict__ hinhi,
          const __nv_bfloat16* __restrict__ hinlo,
          const float* __restrict__ wdA,
          float* __restrict__ out) {
    int e   = SHARED ? 0 : blockIdx.z;
    int cnt = SHARED ? T_TOK : g_cnt[e];
    int m0  = blockIdx.y * 128;
    if (m0 >= cnt) return;
    int n0  = blockIdx.x * 64;
    const float* wd = wdA + (SHARED ? 0 : (size_t)e * FDIM * DDIM);

    extern __shared__ char dyn[];
    __shared__ int toks[128];
    int tid = threadIdx.x;
    if (tid < 128) {
        int m = m0 + tid;
        toks[tid] = (m < cnt) ? (SHARED ? m : g_list[e * T_TOK + m]) : -1;
    }
    __syncthreads();

    uint32_t smb = smem_u32(dyn);

    const __nv_bfloat16* ahsrc[2];
    const __nv_bfloat16* alsrc[2];
    int apred[2];
    uint32_t adst[2];
#pragma unroll
    for (int i = 0; i < 2; i++) {
        int s = tid * 2 + i;
        int row = s >> 2, q = s & 3;
        int tk = toks[row];
        apred[i] = (tk >= 0) ? 16 : 0;
        size_t off = (tk >= 0) ? ((size_t)tk * FDIM + q * 8) : 0;
        ahsrc[i] = hinhi + off;
        alsrc[i] = hinlo + off;
        adst[i]  = row * 80 + q * 16;
    }
    const float* bsrc[2];
    uint32_t bdst[2];
#pragma unroll
    for (int i = 0; i < 2; i++) {
        int s = tid + 256 * i;
        int row = s >> 4, chk = s & 15;
        bsrc[i] = wd + (size_t)row * DDIM + n0 + chk * 4;
        bdst[i] = (row * BS_STRIDE_DN + chk * 4) * 4;
    }

    auto load_stage = [&](int kc, int st) {
        int k0 = kc * 32;
        uint32_t ah = smb + DN_AHI + st * A16_STAGE;
        uint32_t al = smb + DN_ALO + st * A16_STAGE;
#pragma unroll
        for (int i = 0; i < 2; i++) {
            cpa16(ah + adst[i], ahsrc[i] + k0, apred[i]);
            cpa16(al + adst[i], alsrc[i] + k0, apred[i]);
        }
        uint32_t bb = smb + DN_BF + st * BF32_STAGE_DN;
#pragma unroll
        for (int i = 0; i < 2; i++)
            cpa16(bb + bdst[i], bsrc[i] + (size_t)k0 * DDIM, 16);
        CP_COMMIT();
    };

    int wid = tid >> 5, lane = tid & 31;
    int wm = (wid >> 1) * 32;
    int wn = (wid & 1) * 32;
    int gr = lane >> 2, gc = lane & 3;

    float acc[2][4][4];
#pragma unroll
    for (int mt = 0; mt < 2; mt++)
#pragma unroll
        for (int nt = 0; nt < 4; nt++)
#pragma unroll
            for (int j = 0; j < 4; j++) acc[mt][nt][j] = 0.f;

    const int NKC = FDIM / 32;  // 128
    load_stage(0, 0);
    load_stage(1, 1);

    int ccol = tid >> 2, ckq = (tid & 3) * 8;
    uint32_t* bhu = (uint32_t*)(dyn + DN_BHI);
    uint32_t* blu = (uint32_t*)(dyn + DN_BLO);

    for (int kc = 0; kc < NKC; kc++) {
        CP_WAIT1();
        __syncthreads();
        if (kc + 2 < NKC) load_stage(kc + 2, (kc + 2) % NSTG);

        {
            const float* Bf = (const float*)(dyn + DN_BF + (kc % NSTG) * BF32_STAGE_DN);
#pragma unroll
            for (int k2 = 0; k2 < 4; k2++) {
                float f0 = Bf[(ckq + 2 * k2) * BS_STRIDE_DN + ccol];
                float f1 = Bf[(ckq + 2 * k2 + 1) * BS_STRIDE_DN + ccol];
                uint32_t hi, lo;
                bf16_split2(make_float2(f0, f1), hi, lo);
                bhu[ccol * 20 + (ckq >> 1) + k2] = hi;
                blu[ccol * 20 + (ckq >> 1) + k2] = lo;
            }
        }
        __syncthreads();

        const __nv_bfloat16* Ah = (const __nv_bfloat16*)(dyn + DN_AHI + (kc % NSTG) * A16_STAGE);
        const __nv_bfloat16* Al = (const __nv_bfloat16*)(dyn + DN_ALO + (kc % NSTG) * A16_STAGE);
        const __nv_bfloat16* Bh = (const __nv_bfloat16*)(dyn + DN_BHI);
        const __nv_bfloat16* Bl = (const __nv_bfloat16*)(dyn + DN_BLO);
#pragma unroll
        for (int ks = 0; ks < 2; ks++) {
            uint32_t a_hi[2][4], a_lo[2][4];
#pragma unroll
            for (int mt = 0; mt < 2; mt++) {
                int base = (wm + mt * 16 + gr) * BF_STRIDE + ks * 16 + gc * 2;
                a_hi[mt][0] = *(const uint32_t*)(Ah + base);
                a_hi[mt][1] = *(const uint32_t*)(Ah + base + 8 * BF_STRIDE);
                a_hi[mt][2] = *(const uint32_t*)(Ah + base + 8);
                a_hi[mt][3] = *(const uint32_t*)(Ah + base + 8 * BF_STRIDE + 8);
                a_lo[mt][0] = *(const uint32_t*)(Al + base);
                a_lo[mt][1] = *(const uint32_t*)(Al + base + 8 * BF_STRIDE);
                a_lo[mt][2] = *(const uint32_t*)(Al + base + 8);
                a_lo[mt][3] = *(const uint32_t*)(Al + base + 8 * BF_STRIDE + 8);
            }
#pragma unroll
            for (int nt = 0; nt < 4; nt++) {
                int col = wn + nt * 8 + gr;
                int bbase = col * BF_STRIDE + ks * 16 + gc * 2;
                uint32_t b_hi[2], b_lo[2];
                b_hi[0] = *(const uint32_t*)(Bh + bbase);
                b_hi[1] = *(const uint32_t*)(Bh + bbase + 8);
                b_lo[0] = *(const uint32_t*)(Bl + bbase);
                b_lo[1] = *(const uint32_t*)(Bl + bbase + 8);
#pragma unroll
                for (int mt = 0; mt < 2; mt++) {
                    MMA_BF16(acc[mt][nt], a_hi[mt], b_lo);
                    MMA_BF16(acc[mt][nt], a_lo[mt], b_hi);
                    MMA_BF16(acc[mt][nt], a_hi[mt], b_hi);
                }
            }
        }
        __syncthreads();
    }

#pragma unroll
    for (int mt = 0; mt < 2; mt++) {
#pragma unroll
        for (int half = 0; half < 2; half++) {
            int row = wm + mt * 16 + gr + half * 8;
            int tk = toks[row];
            if (tk < 0) continue;
            float wt = SHARED ? 1.f : g_w[tk];
            float* orow = out + (size_t)tk * DDIM + n0 + wn;
#pragma unroll
            for (int nt = 0; nt < 4; nt++) {
                float2 v;
                v.x = wt * acc[mt][nt][half * 2 + 0];
                v.y = wt * acc[mt][nt][half * 2 + 1];
                float* op = orow + nt * 8 + gc * 2;
                if (SHARED) {
                    float2 p = *(float2*)op;
                    v.x += p.x; v.y += p.y;
                }
                *(float2*)op = v;
            }
        }
    }
}

// ================= host =================
extern "C" void kernel_launch(void* const* d_in, const int* in_sizes, int n_in,
                              void* d_out, int out_size) {
    const float* x   = (const float*)d_in[0];
    const float* rw  = (const float*)d_in[1];
    const float* wg  = (const float*)d_in[2];
    const float* wu  = (const float*)d_in[3];
    const float* wd  = (const float*)d_in[4];
    const float* wsg = (const float*)d_in[5];
    const float* wsu = (const float*)d_in[6];
    const float* wsd = (const float*)d_in[7];
    float* out = (float*)d_out;

    void *p_hhi = 0, *p_hlo = 0, *p_hshi = 0, *p_hslo = 0;
    cudaGetSymbolAddress(&p_hhi, g_hhi);
    cudaGetSymbolAddress(&p_hlo, g_hlo);
    cudaGetSymbolAddress(&p_hshi, g_hshi);
    cudaGetSymbolAddress(&p_hslo, g_hslo);

    cudaFuncSetAttribute(gu_kernel<false>, cudaFuncAttributeMaxDynamicSharedMemorySize, SMEM_GU);
    cudaFuncSetAttribute(gu_kernel<true>,  cudaFuncAttributeMaxDynamicSharedMemorySize, SMEM_GU);
    cudaFuncSetAttribute(dn_kernel<false>, cudaFuncAttributeMaxDynamicSharedMemorySize, SMEM_DN);
    cudaFuncSetAttribute(dn_kernel<true>,  cudaFuncAttributeMaxDynamicSharedMemorySize, SMEM_DN);

    zero_counts<<<1, 32>>>();
    router_kernel<<<T_TOK / 8, dim3(32, 8)>>>(x, rw);
    scatter_kernel<<<T_TOK / 256, 256>>>();
    convert_x<<<T_TOK * DDIM / 2 / 256, 256>>>(x);

    gu_kernel<false><<<dim3(FDIM / 64, T_TOK / 128, NEXP), 256, SMEM_GU>>>(
        wg, wu, (__nv_bfloat16*)p_hhi, (__nv_bfloat16*)p_hlo);
    dn_kernel<false><<<dim3(DDIM / 64, T_TOK / 128, NEXP), 256, SMEM_DN>>>(
        (const __nv_bfloat16*)p_hhi, (const __nv_bfloat16*)p_hlo, wd, out);

    gu_kernel<true><<<dim3(FDIM / 64, T_TOK / 128, 1), 256, SMEM_GU>>>(
        wsg, wsu, (__nv_bfloat16*)p_hshi, (__nv_bfloat16*)p_hslo);
    dn_kernel<true><<<dim3(DDIM / 64, T_TOK / 128, 1), 256, SMEM_DN>>>(
        (const __nv_bfloat16*)p_hshi, (const __nv_bfloat16*)p_hslo, wsd, out);
}

// round 8
// speedup vs baseline: 1.2475x; 1.2475x over previous
#include <cuda_runtime.h>
#include <cuda_bf16.h>
#include <math.h>
#include <stdint.h>

#define T_TOK 2048
#define DDIM  2048
#define FDIM  4096
#define NEXP  8

#define NSTG 3
#define BS_STRIDE_GU 136 // fp32 B stage: 32 k-rows x 128 cols padded
#define BS_STRIDE_DN 72  // fp32 B stage: 32 k-rows x 64 cols padded
#define BF_STRIDE 40     // bf16 A tile: [row][k], stride 40 halfs
#define A16_STAGE 10240  // 128 rows * 80 B

#define BF32_STAGE_GU (32 * BS_STRIDE_GU * 4)   // 17408
#define BF32_STAGE_DN (32 * BS_STRIDE_DN * 4)   // 9216

// GU smem: A hi | A lo | B fp32
#define GU_AHI 0
#define GU_ALO (NSTG * A16_STAGE)                 // 30720
#define GU_BF  (2 * NSTG * A16_STAGE)             // 61440
#define SMEM_GU (GU_BF + NSTG * BF32_STAGE_GU)    // 113664

#define DN_AHI 0
#define DN_ALO (NSTG * A16_STAGE)
#define DN_BF  (2 * NSTG * A16_STAGE)
#define SMEM_DN (DN_BF + NSTG * BF32_STAGE_DN)    // 89088

// ---- static scratch ----
__device__ int   g_cnt[NEXP];
__device__ int   g_eid[T_TOK];
__device__ float g_w[T_TOK];
__device__ int   g_list[NEXP * T_TOK];
__device__ __nv_bfloat16 g_xhi[(size_t)T_TOK * DDIM];
__device__ __nv_bfloat16 g_xlo[(size_t)T_TOK * DDIM];
__device__ __nv_bfloat16 g_hhi[(size_t)T_TOK * FDIM];
__device__ __nv_bfloat16 g_hlo[(size_t)T_TOK * FDIM];
__device__ __nv_bfloat16 g_hshi[(size_t)T_TOK * FDIM];
__device__ __nv_bfloat16 g_hslo[(size_t)T_TOK * FDIM];

// ---- helpers ----
__device__ __forceinline__ uint32_t smem_u32(const void* p) {
    uint32_t a;
    asm("{ .reg .u64 t; cvta.to.shared.u64 t, %1; cvt.u32.u64 %0, t; }"
        : "=r"(a) : "l"(p));
    return a;
}

__device__ __forceinline__ void cpa16(uint32_t dst, const void* src, int srcsz) {
    asm volatile("cp.async.cg.shared.global [%0], [%1], 16, %2;"
                 :: "r"(dst), "l"(src), "r"(srcsz) : "memory");
}
#define CP_COMMIT() asm volatile("cp.async.commit_group;" ::: "memory")
#define CP_WAIT1()  asm volatile("cp.async.wait_group 1;" ::: "memory")

#define MMA_BF16(d, a, b) \
    asm volatile("mma.sync.aligned.m16n8k16.row.col.f32.bf16.bf16.f32 " \
        "{%0,%1,%2,%3}, {%4,%5,%6,%7}, {%8,%9}, {%0,%1,%2,%3};" \
        : "+f"((d)[0]), "+f"((d)[1]), "+f"((d)[2]), "+f"((d)[3]) \
        : "r"((a)[0]), "r"((a)[1]), "r"((a)[2]), "r"((a)[3]), \
          "r"((b)[0]), "r"((b)[1]))

// split float2 (f.x -> low half, f.y -> high half) into hi bf16x2 + lo residual bf16x2
__device__ __forceinline__ void bf16_split2(float2 f, uint32_t& hi, uint32_t& lo) {
    uint32_t h;
    asm("cvt.rn.bf16x2.f32 %0, %1, %2;" : "=r"(h) : "f"(f.y), "f"(f.x));
    float hx = __uint_as_float(h << 16);
    float hy = __uint_as_float(h & 0xffff0000u);
    asm("cvt.rn.bf16x2.f32 %0, %1, %2;" : "=r"(lo) : "f"(f.y - hy), "f"(f.x - hx));
    hi = h;
}

__device__ __forceinline__ float silu_f(float g) {
    return g / (1.f + __expf(-g));
}

// ---- routing ----
__global__ void zero_counts() {
    if (threadIdx.x < NEXP) g_cnt[threadIdx.x] = 0;
}

__global__ void router_kernel(const float* __restrict__ x,
                              const float* __restrict__ rw) {
    int t = blockIdx.x * blockDim.y + threadIdx.y;
    if (t >= T_TOK) return;
    int lane = threadIdx.x;
    float acc[NEXP];
#pragma unroll
    for (int e = 0; e < NEXP; e++) acc[e] = 0.f;
    const float* xr = x + (size_t)t * DDIM;
    for (int d = lane; d < DDIM; d += 32) {
        float xv = xr[d];
        const float4* r = (const float4*)(rw + (size_t)d * NEXP);
        float4 r0 = r[0], r1 = r[1];
        acc[0] += xv * r0.x; acc[1] += xv * r0.y;
        acc[2] += xv * r0.z; acc[3] += xv * r0.w;
        acc[4] += xv * r1.x; acc[5] += xv * r1.y;
        acc[6] += xv * r1.z; acc[7] += xv * r1.w;
    }
#pragma unroll
    for (int off = 16; off > 0; off >>= 1)
#pragma unroll
        for (int e = 0; e < NEXP; e++)
            acc[e] += __shfl_down_sync(0xffffffffu, acc[e], off);
    if (lane == 0) {
        int best = 0; float bv = acc[0];
#pragma unroll
        for (int e = 1; e < NEXP; e++)
            if (acc[e] > bv) { bv = acc[e]; best = e; }
        g_eid[t] = best;
        g_w[t]   = 1.f / (1.f + expf(-bv));
    }
}

__global__ void scatter_kernel() {
    int t = blockIdx.x * blockDim.x + threadIdx.x;
    if (t < T_TOK) {
        int e = g_eid[t];
        int p = atomicAdd(&g_cnt[e], 1);
        g_list[e * T_TOK + p] = t;
    }
}

__global__ void convert_x(const float* __restrict__ x) {
    int i = blockIdx.x * blockDim.x + threadIdx.x;   // over T*D/2
    float2 f = ((const float2*)x)[i];
    uint32_t hi, lo;
    bf16_split2(f, hi, lo);
    ((uint32_t*)g_xhi)[i] = hi;
    ((uint32_t*)g_xlo)[i] = lo;
}

// ================= gate+up GEMM =================
template<bool SHARED>
__global__ void __launch_bounds__(256, 2)
gu_kernel(const float* __restrict__ wgA,
          const float* __restrict__ wuA,
          __nv_bfloat16* __restrict__ hhi,
          __nv_bfloat16* __restrict__ hlo) {
    int e   = SHARED ? 0 : blockIdx.z;
    int cnt = SHARED ? T_TOK : g_cnt[e];
    int m0  = blockIdx.y * 128;
    if (m0 >= cnt) return;
    int n0  = blockIdx.x * 64;
    const float* wg = wgA + (SHARED ? 0 : (size_t)e * DDIM * FDIM);
    const float* wu = wuA + (SHARED ? 0 : (size_t)e * DDIM * FDIM);

    extern __shared__ char dyn[];
    __shared__ int toks[128];
    int tid = threadIdx.x;
    if (tid < 128) {
        int m = m0 + tid;
        toks[tid] = (m < cnt) ? (SHARED ? m : g_list[e * T_TOK + m]) : -1;
    }
    __syncthreads();

    uint32_t smb = smem_u32(dyn);

    // A loads (bf16 hi/lo): 512 16B-chunks per array, 2/thread/array
    const __nv_bfloat16* ahsrc[2];
    const __nv_bfloat16* alsrc[2];
    int apred[2];
    uint32_t adst[2];
#pragma unroll
    for (int i = 0; i < 2; i++) {
        int s = tid * 2 + i;
        int row = s >> 2, q = s & 3;
        int tk = toks[row];
        apred[i] = (tk >= 0) ? 16 : 0;
        size_t off = (tk >= 0) ? ((size_t)tk * DDIM + q * 8) : 0;
        ahsrc[i] = g_xhi + off;
        alsrc[i] = g_xlo + off;
        adst[i]  = row * 80 + q * 16;
    }
    // B loads (fp32): 1024 chunks, 4/thread; cols 0-63 gate, 64-127 up
    const float* bsrc[4];
    uint32_t bdst[4];
#pragma unroll
    for (int i = 0; i < 4; i++) {
        int s = tid + 256 * i;
        int row = s >> 5, chk = s & 31;
        const float* base = (chk < 16) ? (wg + n0 + chk * 4)
                                       : (wu + n0 + (chk - 16) * 4);
        bsrc[i] = base + (size_t)row * FDIM;
        bdst[i] = (row * BS_STRIDE_GU + (chk & 15) * 4 + (chk < 16 ? 0 : 64)) * 4;
    }

    auto load_stage = [&](int kc, int st) {
        int k0 = kc * 32;
        uint32_t ah = smb + GU_AHI + st * A16_STAGE;
        uint32_t al = smb + GU_ALO + st * A16_STAGE;
#pragma unroll
        for (int i = 0; i < 2; i++) {
            cpa16(ah + adst[i], ahsrc[i] + k0, apred[i]);
            cpa16(al + adst[i], alsrc[i] + k0, apred[i]);
        }
        uint32_t bb = smb + GU_BF + st * BF32_STAGE_GU;
#pragma unroll
        for (int i = 0; i < 4; i++)
            cpa16(bb + bdst[i], bsrc[i] + (size_t)k0 * FDIM, 16);
        CP_COMMIT();
    };

    int wid = tid >> 5, lane = tid & 31;
    int wm = (wid >> 1) * 32;
    int wn = (wid & 1) * 32;
    int gr = lane >> 2, gc = lane & 3;

    float acc[2][8][4];
#pragma unroll
    for (int mt = 0; mt < 2; mt++)
#pragma unroll
        for (int nt = 0; nt < 8; nt++)
#pragma unroll
            for (int j = 0; j < 4; j++) acc[mt][nt][j] = 0.f;

    const int NKC = DDIM / 32;  // 64
    load_stage(0, 0);
    load_stage(1, 1);

    for (int kc = 0; kc < NKC; kc++) {
        CP_WAIT1();
        __syncthreads();
        if (kc + 2 < NKC) load_stage(kc + 2, (kc + 2) % NSTG);

        const __nv_bfloat16* Ah = (const __nv_bfloat16*)(dyn + GU_AHI + (kc % NSTG) * A16_STAGE);
        const __nv_bfloat16* Al = (const __nv_bfloat16*)(dyn + GU_ALO + (kc % NSTG) * A16_STAGE);
        const float* Bs = (const float*)(dyn + GU_BF + (kc % NSTG) * BF32_STAGE_GU);
#pragma unroll
        for (int ks = 0; ks < 2; ks++) {
            uint32_t a_hi[2][4], a_lo[2][4];
#pragma unroll
            for (int mt = 0; mt < 2; mt++) {
                int base = (wm + mt * 16 + gr) * BF_STRIDE + ks * 16 + gc * 2;
                a_hi[mt][0] = *(const uint32_t*)(Ah + base);
                a_hi[mt][1] = *(const uint32_t*)(Ah + base + 8 * BF_STRIDE);
                a_hi[mt][2] = *(const uint32_t*)(Ah + base + 8);
                a_hi[mt][3] = *(const uint32_t*)(Ah + base + 8 * BF_STRIDE + 8);
                a_lo[mt][0] = *(const uint32_t*)(Al + base);
                a_lo[mt][1] = *(const uint32_t*)(Al + base + 8 * BF_STRIDE);
                a_lo[mt][2] = *(const uint32_t*)(Al + base + 8);
                a_lo[mt][3] = *(const uint32_t*)(Al + base + 8 * BF_STRIDE + 8);
            }
#pragma unroll
            for (int nt = 0; nt < 8; nt++) {
                int col = (nt < 4) ? (wn + nt * 8) : (64 + wn + (nt - 4) * 8);
                const float* bp = Bs + (ks * 16 + gc * 2) * BS_STRIDE_GU + col + gr;
                uint32_t b_hi[2], b_lo[2];
                bf16_split2(make_float2(bp[0], bp[BS_STRIDE_GU]),                    b_hi[0], b_lo[0]);
                bf16_split2(make_float2(bp[8 * BS_STRIDE_GU], bp[9 * BS_STRIDE_GU]), b_hi[1], b_lo[1]);
#pragma unroll
                for (int mt = 0; mt < 2; mt++) {
                    MMA_BF16(acc[mt][nt], a_hi[mt], b_lo);
                    MMA_BF16(acc[mt][nt], a_lo[mt], b_hi);
                    MMA_BF16(acc[mt][nt], a_hi[mt], b_hi);
                }
            }
        }
        __syncthreads();
    }

    // epilogue: silu(gate)*up -> h hi/lo bf16
    uint32_t* hh = (uint32_t*)hhi;
    uint32_t* hl = (uint32_t*)hlo;
#pragma unroll
    for (int mt = 0; mt < 2; mt++) {
#pragma unroll
        for (int half = 0; half < 2; half++) {
            int row = wm + mt * 16 + gr + half * 8;
            int tk = toks[row];
            if (tk < 0) continue;
            size_t rb = ((size_t)tk * FDIM + n0 + wn) >> 1;
#pragma unroll
            for (int nt = 0; nt < 4; nt++) {
                float2 v;
                v.x = silu_f(acc[mt][nt][half * 2 + 0]) * acc[mt][nt + 4][half * 2 + 0];
                v.y = silu_f(acc[mt][nt][half * 2 + 1]) * acc[mt][nt + 4][half * 2 + 1];
                uint32_t hi, lo;
                bf16_split2(v, hi, lo);
                size_t idx = rb + ((nt * 8 + gc * 2) >> 1);
                hh[idx] = hi;
                hl[idx] = lo;
            }
        }
    }
}

// ================= down GEMM =================
template<bool SHARED>
__global__ void __launch_bounds__(256, 2)
dn_kernel(const __nv_bfloat16* __restrict__ hinhi,
          const __nv_bfloat16* __restrict__ hinlo,
          const float* __restrict__ wdA,
          float* __restrict__ out) {
    int e   = SHARED ? 0 : blockIdx.z;
    int cnt = SHARED ? T_TOK : g_cnt[e];
    int m0  = blockIdx.y * 128;
    if (m0 >= cnt) return;
    int n0  = blockIdx.x * 64;
    const float* wd = wdA + (SHARED ? 0 : (size_t)e * FDIM * DDIM);

    extern __shared__ char dyn[];
    __shared__ int toks[128];
    int tid = threadIdx.x;
    if (tid < 128) {
        int m = m0 + tid;
        toks[tid] = (m < cnt) ? (SHARED ? m : g_list[e * T_TOK + m]) : -1;
    }
    __syncthreads();

    uint32_t smb = smem_u32(dyn);

    const __nv_bfloat16* ahsrc[2];
    const __nv_bfloat16* alsrc[2];
    int apred[2];
    uint32_t adst[2];
#pragma unroll
    for (int i = 0; i < 2; i++) {
        int s = tid * 2 + i;
        int row = s >> 2, q = s & 3;
        int tk = toks[row];
        apred[i] = (tk >= 0) ? 16 : 0;
        size_t off = (tk >= 0) ? ((size_t)tk * FDIM + q * 8) : 0;
        ahsrc[i] = hinhi + off;
        alsrc[i] = hinlo + off;
        adst[i]  = row * 80 + q * 16;
    }
    const float* bsrc[2];
    uint32_t bdst[2];
#pragma unroll
    for (int i = 0; i < 2; i++) {
        int s = tid + 256 * i;
        int row = s >> 4, chk = s & 15;
        bsrc[i] = wd + (size_t)row * DDIM + n0 + chk * 4;
        bdst[i] = (row * BS_STRIDE_DN + chk * 4) * 4;
    }

    auto load_stage = [&](int kc, int st) {
        int k0 = kc * 32;
        uint32_t ah = smb + DN_AHI + st * A16_STAGE;
        uint32_t al = smb + DN_ALO + st * A16_STAGE;
#pragma unroll
        for (int i = 0; i < 2; i++) {
            cpa16(ah + adst[i], ahsrc[i] + k0, apred[i]);
            cpa16(al + adst[i], alsrc[i] + k0, apred[i]);
        }
        uint32_t bb = smb + DN_BF + st * BF32_STAGE_DN;
#pragma unroll
        for (int i = 0; i < 2; i++)
            cpa16(bb + bdst[i], bsrc[i] + (size_t)k0 * DDIM, 16);
        CP_COMMIT();
    };

    int wid = tid >> 5, lane = tid & 31;
    int wm = (wid >> 1) * 32;
    int wn = (wid & 1) * 32;
    int gr = lane >> 2, gc = lane & 3;

    float acc[2][4][4];
#pragma unroll
    for (int mt = 0; mt < 2; mt++)
#pragma unroll
        for (int nt = 0; nt < 4; nt++)
#pragma unroll
            for (int j = 0; j < 4; j++) acc[mt][nt][j] = 0.f;

    const int NKC = FDIM / 32;  // 128
    load_stage(0, 0);
    load_stage(1, 1);

    for (int kc = 0; kc < NKC; kc++) {
        CP_WAIT1();
        __syncthreads();
        if (kc + 2 < NKC) load_stage(kc + 2, (kc + 2) % NSTG);

        const __nv_bfloat16* Ah = (const __nv_bfloat16*)(dyn + DN_AHI + (kc % NSTG) * A16_STAGE);
        const __nv_bfloat16* Al = (const __nv_bfloat16*)(dyn + DN_ALO + (kc % NSTG) * A16_STAGE);
        const float* Bs = (const float*)(dyn + DN_BF + (kc % NSTG) * BF32_STAGE_DN);
#pragma unroll
        for (int ks = 0; ks < 2; ks++) {
            uint32_t a_hi[2][4], a_lo[2][4];
#pragma unroll
            for (int mt = 0; mt < 2; mt++) {
                int base = (wm + mt * 16 + gr) * BF_STRIDE + ks * 16 + gc * 2;
                a_hi[mt][0] = *(const uint32_t*)(Ah + base);
                a_hi[mt][1] = *(const uint32_t*)(Ah + base + 8 * BF_STRIDE);
                a_hi[mt][2] = *(const uint32_t*)(Ah + base + 8);
                a_hi[mt][3] = *(const uint32_t*)(Ah + base + 8 * BF_STRIDE + 8);
                a_lo[mt][0] = *(const uint32_t*)(Al + base);
                a_lo[mt][1] = *(const uint32_t*)(Al + base + 8 * BF_STRIDE);
                a_lo[mt][2] = *(const uint32_t*)(Al + base + 8);
                a_lo[mt][3] = *(const uint32_t*)(Al + base + 8 * BF_STRIDE + 8);
            }
#pragma unroll
            for (int nt = 0; nt < 4; nt++) {
                const float* bp = Bs + (ks * 16 + gc * 2) * BS_STRIDE_DN + wn + nt * 8 + gr;
                uint32_t b_hi[2], b_lo[2];
                bf16_split2(make_float2(bp[0], bp[BS_STRIDE_DN]),                    b_hi[0], b_lo[0]);
                bf16_split2(make_float2(bp[8 * BS_STRIDE_DN], bp[9 * BS_STRIDE_DN]), b_hi[1], b_lo[1]);
#pragma unroll
                for (int mt = 0; mt < 2; mt++) {
                    MMA_BF16(acc[mt][nt], a_hi[mt], b_lo);
                    MMA_BF16(acc[mt][nt], a_lo[mt], b_hi);
                    MMA_BF16(acc[mt][nt], a_hi[mt], b_hi);
                }
            }
        }
        __syncthreads();
    }

#pragma unroll
    for (int mt = 0; mt < 2; mt++) {
#pragma unroll
        for (int half = 0; half < 2; half++) {
            int row = wm + mt * 16 + gr + half * 8;
            int tk = toks[row];
            if (tk < 0) continue;
            float wt = SHARED ? 1.f : g_w[tk];
            float* orow = out + (size_t)tk * DDIM + n0 + wn;
#pragma unroll
            for (int nt = 0; nt < 4; nt++) {
                float2 v;
                v.x = wt * acc[mt][nt][half * 2 + 0];
                v.y = wt * acc[mt][nt][half * 2 + 1];
                float* op = orow + nt * 8 + gc * 2;
                if (SHARED) {
                    float2 p = *(float2*)op;
                    v.x += p.x; v.y += p.y;
                }
                *(float2*)op = v;
            }
        }
    }
}

// ================= host =================
extern "C" void kernel_launch(void* const* d_in, const int* in_sizes, int n_in,
                              void* d_out, int out_size) {
    const float* x   = (const float*)d_in[0];
    const float* rw  = (const float*)d_in[1];
    const float* wg  = (const float*)d_in[2];
    const float* wu  = (const float*)d_in[3];
    const float* wd  = (const float*)d_in[4];
    const float* wsg = (const float*)d_in[5];
    const float* wsu = (const float*)d_in[6];
    const float* wsd = (const float*)d_in[7];
    float* out = (float*)d_out;

    void *p_hhi = 0, *p_hlo = 0, *p_hshi = 0, *p_hslo = 0;
    cudaGetSymbolAddress(&p_hhi, g_hhi);
    cudaGetSymbolAddress(&p_hlo, g_hlo);
    cudaGetSymbolAddress(&p_hshi, g_hshi);
    cudaGetSymbolAddress(&p_hslo, g_hslo);

    cudaFuncSetAttribute(gu_kernel<false>, cudaFuncAttributeMaxDynamicSharedMemorySize, SMEM_GU);
    cudaFuncSetAttribute(gu_kernel<true>,  cudaFuncAttributeMaxDynamicSharedMemorySize, SMEM_GU);
    cudaFuncSetAttribute(dn_kernel<false>, cudaFuncAttributeMaxDynamicSharedMemorySize, SMEM_DN);
    cudaFuncSetAttribute(dn_kernel<true>,  cudaFuncAttributeMaxDynamicSharedMemorySize, SMEM_DN);

    zero_counts<<<1, 32>>>();
    router_kernel<<<T_TOK / 8, dim3(32, 8)>>>(x, rw);
    scatter_kernel<<<T_TOK / 256, 256>>>();
    convert_x<<<T_TOK * DDIM / 2 / 256, 256>>>(x);

    gu_kernel<false><<<dim3(FDIM / 64, T_TOK / 128, NEXP), 256, SMEM_GU>>>(
        wg, wu, (__nv_bfloat16*)p_hhi, (__nv_bfloat16*)p_hlo);
    dn_kernel<false><<<dim3(DDIM / 64, T_TOK / 128, NEXP), 256, SMEM_DN>>>(
        (const __nv_bfloat16*)p_hhi, (const __nv_bfloat16*)p_hlo, wd, out);

    gu_kernel<true><<<dim3(FDIM / 64, T_TOK / 128, 1), 256, SMEM_GU>>>(
        wsg, wsu, (__nv_bfloat16*)p_hshi, (__nv_bfloat16*)p_hslo);
    dn_kernel<true><<<dim3(DDIM / 64, T_TOK / 128, 1), 256, SMEM_DN>>>(
        (const __nv_bfloat16*)p_hshi, (const __nv_bfloat16*)p_hslo, wsd, out);
}